// round 11
// baseline (speedup 1.0000x reference)
#include <cuda_runtime.h>
#include <cuda_fp16.h>
#include <cstdint>
#include <math.h>

#define T_TOK    4096
#define DM       1024
#define DH       4096
#define NE       8
#define NASSIGN  (T_TOK * 2)

#define KC    32
#define PA    40           // A smem pitch (fp16): 32 + 8 pad
#define PB    264          // B smem pitch (fp16): 256 + 8 pad
#define NSTG  4

// stage layout (bytes)
#define ST_AH    0
#define ST_BH    10240     // 128*PA*2
#define ST_BYTES 27136     // + 32*PB*2 = 16896
#define SM_HDR   2048
#define SMEM_TOTAL (SM_HDR + NSTG * ST_BYTES)   // 110592

#define INVALID_ROW 0xFFFFFFFFu
#define N4X (T_TOK * DM / 4)
#define N4W (NE * DM * DH / 4)

// ---------------- static device scratch ----------------
__device__ __half g_xh [(size_t)T_TOK * DM];
__device__ __half g_W1h[(size_t)NE * DM * DH];
__device__ __half g_W2h[(size_t)NE * DH * DM];
__device__ __half g_Hh [(size_t)NASSIGN * DH];
__device__ int   g_tok[NASSIGN];
__device__ float g_wgt[NASSIGN];
__device__ int   g_eid[NASSIGN];
__device__ float g_ew [NASSIGN];
__device__ int   g_cnt[NE];
__device__ int   g_off[NE];

// ---------------- helpers ----------------
__device__ __forceinline__ uint32_t smem_u32(const void* p) {
    uint32_t a;
    asm("{ .reg .u64 t; cvta.to.shared.u64 t, %1; cvt.u32.u64 %0, t; }" : "=r"(a) : "l"(p));
    return a;
}
__device__ __forceinline__ uint2 pack4_h(float4 v) {
    __half2 h01 = __halves2half2(__float2half(v.x), __float2half(v.y));
    __half2 h23 = __halves2half2(__float2half(v.z), __float2half(v.w));
    uint2 r;
    r.x = *(uint32_t*)&h01; r.y = *(uint32_t*)&h23;
    return r;
}
__device__ __forceinline__ void ldsm_x4(uint32_t (&d)[4], uint32_t addr) {
    asm volatile("ldmatrix.sync.aligned.m8n8.x4.shared.b16 {%0,%1,%2,%3}, [%4];"
        : "=r"(d[0]), "=r"(d[1]), "=r"(d[2]), "=r"(d[3]) : "r"(addr));
}
__device__ __forceinline__ void ldsm_x4t(uint32_t (&d)[4], uint32_t addr) {
    asm volatile("ldmatrix.sync.aligned.m8n8.x4.trans.shared.b16 {%0,%1,%2,%3}, [%4];"
        : "=r"(d[0]), "=r"(d[1]), "=r"(d[2]), "=r"(d[3]) : "r"(addr));
}
__device__ __forceinline__ void mma_f16(float (&d)[4], const uint32_t (&a)[4],
                                         uint32_t b0, uint32_t b1) {
    asm volatile("mma.sync.aligned.m16n8k16.row.col.f32.f16.f16.f32 "
        "{%0,%1,%2,%3},{%4,%5,%6,%7},{%8,%9},{%0,%1,%2,%3};"
        : "+f"(d[0]), "+f"(d[1]), "+f"(d[2]), "+f"(d[3])
        : "r"(a[0]), "r"(a[1]), "r"(a[2]), "r"(a[3]), "r"(b0), "r"(b1));
}
__device__ __forceinline__ void cp16(uint32_t dst, const void* src, uint32_t sz) {
    asm volatile("cp.async.cg.shared.global [%0], [%1], 16, %2;"
                 :: "r"(dst), "l"(src), "r"(sz));
}
#define CP_COMMIT() asm volatile("cp.async.commit_group;" ::: "memory")
#define CP_WAIT2()  asm volatile("cp.async.wait_group 2;" ::: "memory")

// ---------------- issue one KC=32 x (128 A-rows, 256 B-cols) chunk (256 thr) ----------------
__device__ __forceinline__ void issue_chunk(
    uint32_t st, const __half* __restrict__ Ah, const uint32_t* __restrict__ rowoff,
    const __half* __restrict__ Bh, int ldb, int n0, int k0, int tid)
{
    // A: 128 rows x 32 k; thread -> (row = tid>>1, 32B-half = tid&1): 2 x cp16
    const int ar = tid >> 1, ahf = tid & 1;
    uint32_t ro = rowoff[ar];
    uint32_t sz = (ro != INVALID_ROW) ? 16u : 0u;
    uint32_t roc = (ro != INVALID_ROW) ? ro : 0u;
    const __half* sa = Ah + roc + k0 + ahf * 16;
    uint32_t da = st + ST_AH + ar * (PA * 2) + ahf * 32;
    cp16(da,      sa,     sz);
    cp16(da + 16, sa + 8, sz);

    // B: 32 k-rows x 256 n; thread -> (krow = tid>>3, 4 x 16B segs: tid&7 + {0,8,16,24})
    const int br = tid >> 3, bs = tid & 7;
    const __half* sbh = Bh + (size_t)(k0 + br) * ldb + n0;
    uint32_t dbh = st + ST_BH + br * (PB * 2);
#pragma unroll
    for (int s = 0; s < 4; s++)
        cp16(dbh + (bs + s * 8) * 16, sbh + (bs + s * 8) * 8, 16u);
}

// ---------------- compute one chunk (pure fp16), warp tile 64x64 ----------------
__device__ __forceinline__ void compute_chunk(
    uint32_t aH, uint32_t bH, float (&acc)[4][8][4])
{
#pragma unroll
    for (int ks = 0; ks < 2; ks++) {
        uint32_t ah[4][4];
#pragma unroll
        for (int mi = 0; mi < 4; mi++)
            ldsm_x4(ah[mi], aH + ks * 32 + mi * (16 * PA * 2));
#pragma unroll
        for (int njp = 0; njp < 2; njp++) {       // two n32 halves of the n64 tile
            uint32_t bh[2][4];
#pragma unroll
            for (int j = 0; j < 2; j++)
                ldsm_x4t(bh[j], bH + ks * (16 * PB * 2) + (njp * 2 + j) * 32);
#pragma unroll
            for (int mi = 0; mi < 4; mi++)
#pragma unroll
                for (int j = 0; j < 2; j++)
#pragma unroll
                    for (int h = 0; h < 2; h++)
                        mma_f16(acc[mi][njp * 4 + j * 2 + h], ah[mi],
                                bh[j][h * 2], bh[j][h * 2 + 1]);
        }
    }
}

// ---------------- shared mainloop (256 threads, 8 warps, CTA 128x256) ----------------
__device__ __forceinline__ void mainloop(
    char* dsm, const __half* Ah, const __half* Bh,
    int ldb, int n0, int nch, float (&acc)[4][8][4])
{
    const int tid = threadIdx.x;
    const uint32_t sb = smem_u32(dsm);
    const uint32_t* rowoff = (const uint32_t*)dsm;

    const int lane = tid & 31, w = tid >> 5;
    const int m_warp = (w >> 2) * 64, n_warp = (w & 3) * 64;
    const int g = lane >> 3, r = lane & 7;
    const uint32_t a_lane = (uint32_t)(((m_warp + (g & 1) * 8 + r) * PA + (g >> 1) * 8) * 2);
    const uint32_t b_lane = (uint32_t)((((g & 1) * 8 + r) * PB + n_warp + (g >> 1) * 8) * 2);

    uint32_t stg[NSTG];
#pragma unroll
    for (int s = 0; s < NSTG; s++) stg[s] = sb + SM_HDR + s * ST_BYTES;

    issue_chunk(stg[0], Ah, rowoff, Bh, ldb, n0, 0, tid);
    CP_COMMIT();
    issue_chunk(stg[1], Ah, rowoff, Bh, ldb, n0, KC, tid);
    CP_COMMIT();

    for (int c = 0; c < nch; c++) {
        if (c + 2 < nch)
            issue_chunk(stg[(c + 2) & 3], Ah, rowoff, Bh, ldb, n0, (c + 2) * KC, tid);
        CP_COMMIT();
        CP_WAIT2();
        __syncthreads();
        uint32_t st = stg[c & 3];
        compute_chunk(st + ST_AH + a_lane, st + ST_BH + b_lane, acc);
    }
}

// ---------------- fused conversion: x, W1, W2 -> fp16 ----------------
__global__ void k_conv_all(const float4* __restrict__ x, const float4* __restrict__ W1,
                           const float4* __restrict__ W2,
                           uint2* __restrict__ xh,
                           uint2* __restrict__ w1h, uint2* __restrict__ w2h) {
    int i = blockIdx.x * blockDim.x + threadIdx.x;
    if (i < N4X) {
        xh[i] = pack4_h(x[i]);
    } else if (i < N4X + N4W) {
        int j = i - N4X;
        w1h[j] = pack4_h(W1[j]);
    } else if (i < N4X + 2 * N4W) {
        int j = i - N4X - N4W;
        w2h[j] = pack4_h(W2[j]);
    }
}

// ---------------- gating (+ output zeroing folded in) ----------------
__global__ void k_gate(const float* __restrict__ x, const float* __restrict__ Wg,
                       const float* __restrict__ bg, float* __restrict__ out) {
    {
        float4* o4 = (float4*)out;
        int base = blockIdx.x * 2048;
#pragma unroll
        for (int i = 0; i < 8; i++)
            o4[base + i * 256 + threadIdx.x] = make_float4(0.f, 0.f, 0.f, 0.f);
    }
    float* out_logits = out + (size_t)T_TOK * DM;
    int warp = threadIdx.x >> 5, lane = threadIdx.x & 31;
    int t = blockIdx.x * 8 + warp;
    if (t >= T_TOK) return;
    const float* xr = x + (size_t)t * DM;
    float acc[NE];
#pragma unroll
    for (int e = 0; e < NE; e++) acc[e] = 0.f;
    for (int k = lane; k < DM; k += 32) {
        float xv = xr[k];
        const float* w = Wg + (size_t)k * NE;
#pragma unroll
        for (int e = 0; e < NE; e++) acc[e] += xv * w[e];
    }
#pragma unroll
    for (int e = 0; e < NE; e++)
#pragma unroll
        for (int o = 16; o; o >>= 1) acc[e] += __shfl_xor_sync(0xffffffffu, acc[e], o);
    if (lane == 0) {
#pragma unroll
        for (int e = 0; e < NE; e++) {
            acc[e] += bg[e];
            out_logits[(size_t)t * NE + e] = acc[e];
        }
        int b0 = 0;
#pragma unroll
        for (int e = 1; e < NE; e++) if (acc[e] > acc[b0]) b0 = e;
        int b1 = (b0 == 0) ? 1 : 0;
#pragma unroll
        for (int e = 0; e < NE; e++) if (e != b0 && acc[e] > acc[b1]) b1 = e;
        float ex = expf(acc[b1] - acc[b0]);
        float w0 = 1.f / (1.f + ex);
        float w1 = ex * w0;
        g_eid[2 * t] = b0;     g_ew[2 * t] = w0;
        g_eid[2 * t + 1] = b1; g_ew[2 * t + 1] = w1;
    }
}

// ---------------- routing ----------------
__global__ void k_route() {
    __shared__ int s_cnt[NE], s_cur[NE];
    int tid = threadIdx.x;
    if (tid < NE) s_cnt[tid] = 0;
    __syncthreads();
    for (int a = tid; a < NASSIGN; a += blockDim.x)
        atomicAdd(&s_cnt[g_eid[a]], 1);
    __syncthreads();
    if (tid == 0) {
        int s = 0;
#pragma unroll
        for (int e = 0; e < NE; e++) {
            s_cur[e] = s;
            g_cnt[e] = s_cnt[e]; g_off[e] = s;
            s += s_cnt[e];
        }
    }
    __syncthreads();
    for (int a = tid; a < NASSIGN; a += blockDim.x) {
        int e = g_eid[a];
        int pos = atomicAdd(&s_cur[e], 1);
        g_tok[pos] = a >> 1;
        g_wgt[pos] = g_ew[a];
    }
}

// ---------------- GEMM1: H(fp16) = relu(x @ W1[e] + b1[e]) ----------------
__global__ void __launch_bounds__(256, 1)
k_gemm1_mma(const float* __restrict__ b1) {
    extern __shared__ char dsm[];
    const int e = blockIdx.z;
    const int cnt = g_cnt[e];
    const int m0 = blockIdx.y * 128;
    if (m0 >= cnt) return;
    const int off = g_off[e];
    const int n0 = blockIdx.x * 256;
    const int tid = threadIdx.x;

    uint32_t* rowoff = (uint32_t*)dsm;
    if (tid < 128) {
        int gi = m0 + tid;
        rowoff[tid] = (gi < cnt) ? (uint32_t)(g_tok[off + gi] * DM) : INVALID_ROW;
    }
    __syncthreads();

    float acc[4][8][4];
#pragma unroll
    for (int a = 0; a < 4; a++)
#pragma unroll
        for (int b = 0; b < 8; b++)
#pragma unroll
            for (int c = 0; c < 4; c++) acc[a][b][c] = 0.f;

    mainloop(dsm, g_xh, g_W1h + (size_t)e * DM * DH, DH, n0, DM / KC, acc);

    const int lane = tid & 31, w = tid >> 5;
    const int m_warp = (w >> 2) * 64, n_warp = (w & 3) * 64;
    const float* bb = b1 + (size_t)e * DH;
#pragma unroll
    for (int mi = 0; mi < 4; mi++) {
#pragma unroll
        for (int ni = 0; ni < 8; ni++) {
            int col = n0 + n_warp + ni * 8 + (lane & 3) * 2;
            float bc0 = bb[col], bc1 = bb[col + 1];
#pragma unroll
            for (int hr = 0; hr < 2; hr++) {
                int lr = m_warp + mi * 16 + (lane >> 2) + hr * 8;
                int gi = m0 + lr;
                if (gi < cnt) {
                    float h0 = fmaxf(acc[mi][ni][hr * 2 + 0] + bc0, 0.f);
                    float h1 = fmaxf(acc[mi][ni][hr * 2 + 1] + bc1, 0.f);
                    __half2 hv = __halves2half2(__float2half(h0), __float2half(h1));
                    *(__half2*)(g_Hh + (size_t)(off + gi) * DH + col) = hv;
                }
            }
        }
    }
}

// ---------------- GEMM2 (K-split 2): out[tok] += w * (H @ W2[e] + b2[e]) ----------------
__global__ void __launch_bounds__(256, 1)
k_gemm2_mma(const float* __restrict__ b2, float* __restrict__ out) {
    extern __shared__ char dsm[];
    const int e = blockIdx.z >> 1;
    const int half = blockIdx.z & 1;
    const int cnt = g_cnt[e];
    const int m0 = blockIdx.y * 128;
    if (m0 >= cnt) return;
    const int off = g_off[e];
    const int n0 = blockIdx.x * 256;
    const int koff = half * (DH / 2);
    const int tid = threadIdx.x;

    uint32_t* rowoff = (uint32_t*)dsm;
    int* toks = (int*)(dsm + 512);
    float* wgts = (float*)(dsm + 1024);
    if (tid < 128) {
        int gi = m0 + tid;
        bool v = gi < cnt;
        rowoff[tid] = v ? (uint32_t)((off + gi) * DH + koff) : INVALID_ROW;
        toks[tid] = v ? g_tok[off + gi] : 0;
        wgts[tid] = v ? g_wgt[off + gi] : 0.f;
    }
    __syncthreads();

    float acc[4][8][4];
#pragma unroll
    for (int a = 0; a < 4; a++)
#pragma unroll
        for (int b = 0; b < 8; b++)
#pragma unroll
            for (int c = 0; c < 4; c++) acc[a][b][c] = 0.f;

    mainloop(dsm, g_Hh, g_W2h + (size_t)e * DH * DM + (size_t)koff * DM,
             DM, n0, (DH / 2) / KC, acc);

    const int lane = tid & 31, w = tid >> 5;
    const int m_warp = (w >> 2) * 64, n_warp = (w & 3) * 64;
    const float* bb = b2 + (size_t)e * DM;
#pragma unroll
    for (int mi = 0; mi < 4; mi++) {
#pragma unroll
        for (int ni = 0; ni < 8; ni++) {
            int col = n0 + n_warp + ni * 8 + (lane & 3) * 2;
            float bc0 = half ? 0.f : bb[col];
            float bc1 = half ? 0.f : bb[col + 1];
#pragma unroll
            for (int hr = 0; hr < 2; hr++) {
                int lr = m_warp + mi * 16 + (lane >> 2) + hr * 8;
                int gi = m0 + lr;
                if (gi < cnt) {
                    int tok  = toks[lr];
                    float wv = wgts[lr];
                    float* orow = out + (size_t)tok * DM + col;
                    atomicAdd(orow,     wv * (acc[mi][ni][hr * 2 + 0] + bc0));
                    atomicAdd(orow + 1, wv * (acc[mi][ni][hr * 2 + 1] + bc1));
                }
            }
        }
    }
}

// ---------------- launch ----------------
extern "C" void kernel_launch(void* const* d_in, const int* in_sizes, int n_in,
                              void* d_out, int out_size) {
    const float* x  = (const float*)d_in[0];
    const float* Wg = (const float*)d_in[1];
    const float* bg = (const float*)d_in[2];
    const float* W1 = (const float*)d_in[3];
    const float* b1 = (const float*)d_in[4];
    const float* W2 = (const float*)d_in[5];
    const float* b2 = (const float*)d_in[6];
    float* out = (float*)d_out;

    cudaFuncSetAttribute(k_gemm1_mma, cudaFuncAttributeMaxDynamicSharedMemorySize, SMEM_TOTAL);
    cudaFuncSetAttribute(k_gemm2_mma, cudaFuncAttributeMaxDynamicSharedMemorySize, SMEM_TOTAL);

    void *p_xh, *p_w1h, *p_w2h;
    cudaGetSymbolAddress(&p_xh,  g_xh);
    cudaGetSymbolAddress(&p_w1h, g_W1h);
    cudaGetSymbolAddress(&p_w2h, g_W2h);

    {
        int total = N4X + 2 * N4W;
        k_conv_all<<<(total + 255) / 256, 256>>>(
            (const float4*)x, (const float4*)W1, (const float4*)W2,
            (uint2*)p_xh, (uint2*)p_w1h, (uint2*)p_w2h);
    }
    k_gate<<<T_TOK / 8, 256>>>(x, Wg, bg, out);
    k_route<<<1, 1024>>>();
    k_gemm1_mma<<<dim3(DH / 256, T_TOK / 128, NE), 256, SMEM_TOTAL>>>(b1);
    k_gemm2_mma<<<dim3(DM / 256, T_TOK / 128, NE * 2), 256, SMEM_TOTAL>>>(b2, out);
}